// round 17
// baseline (speedup 1.0000x reference)
#include <cuda_runtime.h>
#include <cuda_bf16.h>

// SwinMSA fused kernel — round 9: tensor-core GEMMs with fragment-ordered weights.
// B=16, WN=4096, S=10, E=96, H=4, dh=24.  WPB=4 windows/CTA, 288 threads, 2 CTAs/SM.
//   prep:    rewrite split-bf16 hi/lo weights into per-lane MMA fragment order
//            (one coalesced LDG.128 per lane = whole B fragment, hi+lo)
//   phase 1: qkv = X @ W_qkv + b   via mma.m16n8k16 (AhBh + AhBl + AlBh)
//   phase 2: attention (scalar fp32, proven), writes split-bf16 context
//   phase 3: out = ctx @ W_o + b_o via mma

#define S_    10
#define E_    96
#define H_    4
#define DH_   24
#define N3_   288
#define WPB   4
#define ROWS  40              // WPB * S_
#define MROWS 48              // padded to 3 m-tiles of 16
#define KA    104             // bf16 row stride of A tiles (conflict-free frag loads)
#define PAD   25
#define WN_   4096
#define NTHREADS 288
#define QSCALE 0.20412414523193154f   // 24^-0.5

typedef unsigned u32;

// fragment-ordered weights: u32 index = frag*128 + lane*4 + reg
//   phase1: frag = (ns*6 + ks)*12 + nt   (ns<3: 96-col strip, ks<6, nt<12)
//           n = 96*ns + 8*nt + g,  k = 16*ks + 2*t (+8 for odd reg), g=lane>>2, t=lane&3
//   phase3: frag = (ns*6 + ks)*4 + nt    (ns<3: 32-col strip, nt<4), n = 32*ns + 8*nt + g
//   reg 0,1 = hi(b0),hi(b1); reg 2,3 = lo(b0),lo(b1)
#define NFRAG_Q (3 * 6 * 12)
#define NFRAG_O (3 * 6 * 4)
__device__ u32 g_WqF[NFRAG_Q * 128];
__device__ u32 g_WoF[NFRAG_O * 128];

__device__ __forceinline__ u32 pack_pair(float w0, float w1, bool lo_part)
{
    const __nv_bfloat16 h0 = __float2bfloat16(w0);
    const __nv_bfloat16 h1 = __float2bfloat16(w1);
    if (!lo_part)
        return (u32)__bfloat16_as_ushort(h0) | ((u32)__bfloat16_as_ushort(h1) << 16);
    const __nv_bfloat16 l0 = __float2bfloat16(w0 - __bfloat162float(h0));
    const __nv_bfloat16 l1 = __float2bfloat16(w1 - __bfloat162float(h1));
    return (u32)__bfloat16_as_ushort(l0) | ((u32)__bfloat16_as_ushort(l1) << 16);
}

__global__ void prep_frag(const float* __restrict__ Wqkv, const float* __restrict__ Wo)
{
    const int idx = blockIdx.x * blockDim.x + threadIdx.x;
    if (idx < NFRAG_Q * 128) {
        const int frag = idx >> 7;
        const int lane = (idx & 127) >> 2;
        const int reg  = idx & 3;
        const int nt = frag % 12, ks = (frag / 12) % 6, ns = frag / 72;
        const int g = lane >> 2, t = lane & 3;
        const int n = 96 * ns + 8 * nt + g;
        const int k = 16 * ks + 2 * t + ((reg & 1) ? 8 : 0);
        g_WqF[idx] = pack_pair(Wqkv[k * N3_ + n], Wqkv[(k + 1) * N3_ + n], reg >= 2);
    }
    if (idx < NFRAG_O * 128) {
        const int frag = idx >> 7;
        const int lane = (idx & 127) >> 2;
        const int reg  = idx & 3;
        const int nt = frag % 4, ks = (frag / 4) % 6, ns = frag / 24;
        const int g = lane >> 2, t = lane & 3;
        const int n = 32 * ns + 8 * nt + g;
        const int k = 16 * ks + 2 * t + ((reg & 1) ? 8 : 0);
        g_WoF[idx] = pack_pair(Wo[k * E_ + n], Wo[(k + 1) * E_ + n], reg >= 2);
    }
}

__device__ __forceinline__ void mma_bf16(float d[4], const u32 a[4], const u32 b0, const u32 b1)
{
    asm volatile("mma.sync.aligned.m16n8k16.row.col.f32.bf16.bf16.f32 "
                 "{%0,%1,%2,%3}, {%4,%5,%6,%7}, {%8,%9}, {%0,%1,%2,%3};"
                 : "+f"(d[0]), "+f"(d[1]), "+f"(d[2]), "+f"(d[3])
                 : "r"(a[0]), "r"(a[1]), "r"(a[2]), "r"(a[3]), "r"(b0), "r"(b1));
}

__device__ __forceinline__ unsigned short bfu(__nv_bfloat16 x) { return __bfloat16_as_ushort(x); }

// smem: A hi/lo + QKV fp32 + posbias = 19968 + 48000 + 320 = 68288 B
#define SMEM_BYTES (2 * MROWS * KA * 2 + 3 * 16 * S_ * PAD * 4 + 80 * 4)

__global__ __launch_bounds__(NTHREADS, 2)
void swin_msa_kernel(const float* __restrict__ X,
                     const float* __restrict__ bqkv,
                     const float* __restrict__ bo,
                     const float* __restrict__ posb,
                     float* __restrict__ out)
{
    extern __shared__ char smem_raw[];
    __nv_bfloat16* sAh = (__nv_bfloat16*)smem_raw;               // [MROWS][KA]
    __nv_bfloat16* sAl = sAh + MROWS * KA;
    float* sQ  = (float*)(sAl + MROWS * KA);                     // [16][S_][PAD]
    float* sK  = sQ + 16 * S_ * PAD;
    float* sV  = sK + 16 * S_ * PAD;
    float* spb = sV + 16 * S_ * PAD;                             // 76 floats

    const int tid = threadIdx.x;
    const long wbase = (long)blockIdx.x * WPB;

    // ---- load X (coalesced float4), split to bf16 hi/lo in smem; zero pad rows ----
    {
        const float4* gX4 = (const float4*)(X + wbase * (S_ * E_));
        for (int i = tid; i < ROWS * E_ / 4; i += NTHREADS) {
            const int r  = i / (E_ / 4);
            const int kq = i - r * (E_ / 4);
            const float4 v = gX4[i];
            const __nv_bfloat16 h0 = __float2bfloat16(v.x);
            const __nv_bfloat16 h1 = __float2bfloat16(v.y);
            const __nv_bfloat16 h2 = __float2bfloat16(v.z);
            const __nv_bfloat16 h3 = __float2bfloat16(v.w);
            const __nv_bfloat16 l0 = __float2bfloat16(v.x - __bfloat162float(h0));
            const __nv_bfloat16 l1 = __float2bfloat16(v.y - __bfloat162float(h1));
            const __nv_bfloat16 l2 = __float2bfloat16(v.z - __bfloat162float(h2));
            const __nv_bfloat16 l3 = __float2bfloat16(v.w - __bfloat162float(h3));
            const u32 hA = (u32)bfu(h0) | ((u32)bfu(h1) << 16);
            const u32 hB = (u32)bfu(h2) | ((u32)bfu(h3) << 16);
            const u32 lA = (u32)bfu(l0) | ((u32)bfu(l1) << 16);
            const u32 lB = (u32)bfu(l2) | ((u32)bfu(l3) << 16);
            *(uint2*)&sAh[r * KA + 4 * kq] = make_uint2(hA, hB);
            *(uint2*)&sAl[r * KA + 4 * kq] = make_uint2(lA, lB);
        }
        // zero pad rows 40..47 of both A tiles (208 u64 each)
        for (int i = tid; i < 416; i += NTHREADS) {
            unsigned long long* p = (i < 208)
                ? (unsigned long long*)(sAh + ROWS * KA)
                : (unsigned long long*)(sAl + ROWS * KA);
            p[i % 208] = 0ull;
        }
        if (tid < (2 * S_ - 1) * H_) spb[tid] = posb[tid];
    }
    __syncthreads();

    const int warp = tid >> 5;
    const int lane = tid & 31;
    const int g = lane >> 2;          // fragment group row
    const int t = lane & 3;           // thread in group

    // ---- phase 1: qkv = X @ Wqkv + b  (warp = m-tile mi x 96-col strip ns) ----
    {
        const int mi = warp % 3;
        const int ns = warp / 3;
        float c[12][4];
        #pragma unroll
        for (int nt = 0; nt < 12; nt++)
            #pragma unroll
            for (int i = 0; i < 4; i++) c[nt][i] = 0.0f;

        #pragma unroll
        for (int ks = 0; ks < 6; ks++) {
            const int k0 = 16 * ks + 2 * t;
            const int ra = 16 * mi + g;
            u32 ah[4], al[4];
            ah[0] = *(const u32*)&sAh[ra * KA + k0];
            ah[1] = *(const u32*)&sAh[(ra + 8) * KA + k0];
            ah[2] = *(const u32*)&sAh[ra * KA + k0 + 8];
            ah[3] = *(const u32*)&sAh[(ra + 8) * KA + k0 + 8];
            al[0] = *(const u32*)&sAl[ra * KA + k0];
            al[1] = *(const u32*)&sAl[(ra + 8) * KA + k0];
            al[2] = *(const u32*)&sAl[ra * KA + k0 + 8];
            al[3] = *(const u32*)&sAl[(ra + 8) * KA + k0 + 8];
            const uint4* fb = (const uint4*)&g_WqF[(((ns * 6 + ks) * 12) * 32 + lane) * 4];
            #pragma unroll 4
            for (int nt = 0; nt < 12; nt++) {
                const uint4 b = fb[nt * 32];     // coalesced: lane*16B within frag
                mma_bf16(c[nt], ah, b.x, b.y);   // Ah*Bh
                mma_bf16(c[nt], ah, b.z, b.w);   // Ah*Bl
                mma_bf16(c[nt], al, b.x, b.y);   // Al*Bh
            }
        }

        // epilogue: +bias, scatter to sQ/sK/sV (c0:(g,2t) c1:(g,2t+1) c2:(g+8,2t) c3:(g+8,2t+1))
        #pragma unroll
        for (int nt = 0; nt < 12; nt++) {
            const int colb = 96 * ns + 8 * nt + 2 * t;
            const float2 bb = *(const float2*)&bqkv[colb];
            #pragma unroll
            for (int i = 0; i < 4; i++) {
                const int row = 16 * mi + g + ((i >> 1) << 3);
                if (row >= ROWS) continue;
                const int col = colb + (i & 1);
                float val = c[nt][i] + ((i & 1) ? bb.y : bb.x);
                const int p = col / E_;
                const int rem = col - p * E_;
                const int h = rem / DH_;
                const int d = rem - h * DH_;
                const int wi = row / S_, r = row - wi * S_;
                const int wh = wi * H_ + h;
                if (p == 0)      sQ[(wh * S_ + r) * PAD + d] = val * QSCALE;
                else if (p == 1) sK[(wh * S_ + r) * PAD + d] = val;
                else             sV[(wh * S_ + r) * PAD + d] = val;
            }
        }
    }
    __syncthreads();

    // ---- phase 2: attention, thread = (wi, h, q); writes split-bf16 ctx into sAh/sAl ----
    if (tid < 16 * S_) {
        const int wi = tid / (H_ * S_);
        const int rem = tid - wi * (H_ * S_);
        const int h = rem / S_;
        const int q = rem - h * S_;

        const float* qrow = &sQ[((wi * H_ + h) * S_ + q) * PAD];
        float qv[DH_];
        #pragma unroll
        for (int d = 0; d < DH_; d++) qv[d] = qrow[d];

        const bool masked = (((wbase + wi) & (WN_ - 1)) == (WN_ - 1));

        float row[S_];
        #pragma unroll
        for (int kk = 0; kk < S_; kk++) {
            const float* krow = &sK[((wi * H_ + h) * S_ + kk) * PAD];
            float s = 0.0f;
            #pragma unroll
            for (int d = 0; d < DH_; d++) s += qv[d] * krow[d];
            s += spb[(kk - q + S_ - 1) * H_ + h];
            if (masked && ((q < 5) != (kk < 5))) s -= 100.0f;
            row[kk] = s;
        }

        float m = row[0];
        #pragma unroll
        for (int kk = 1; kk < S_; kk++) m = fmaxf(m, row[kk]);
        float sum = 0.0f;
        #pragma unroll
        for (int kk = 0; kk < S_; kk++) { row[kk] = __expf(row[kk] - m); sum += row[kk]; }
        const float inv = 1.0f / sum;

        const float* vbase = &sV[(wi * H_ + h) * S_ * PAD];
        const int crow = wi * S_ + q;
        #pragma unroll
        for (int d = 0; d < DH_; d++) {
            float o = 0.0f;
            #pragma unroll
            for (int kk = 0; kk < S_; kk++) o += row[kk] * vbase[kk * PAD + d];
            o *= inv;
            const __nv_bfloat16 oh = __float2bfloat16(o);
            sAh[crow * KA + h * DH_ + d] = oh;
            sAl[crow * KA + h * DH_ + d] = __float2bfloat16(o - __bfloat162float(oh));
        }
    }
    __syncthreads();

    // ---- phase 3: out = ctx @ Wo + b  (warp = m-tile mi x 32-col strip ns) ----
    {
        const int mi = warp % 3;
        const int ns = warp / 3;
        float c[4][4];
        #pragma unroll
        for (int nt = 0; nt < 4; nt++)
            #pragma unroll
            for (int i = 0; i < 4; i++) c[nt][i] = 0.0f;

        #pragma unroll
        for (int ks = 0; ks < 6; ks++) {
            const int k0 = 16 * ks + 2 * t;
            const int ra = 16 * mi + g;
            u32 ah[4], al[4];
            ah[0] = *(const u32*)&sAh[ra * KA + k0];
            ah[1] = *(const u32*)&sAh[(ra + 8) * KA + k0];
            ah[2] = *(const u32*)&sAh[ra * KA + k0 + 8];
            ah[3] = *(const u32*)&sAh[(ra + 8) * KA + k0 + 8];
            al[0] = *(const u32*)&sAl[ra * KA + k0];
            al[1] = *(const u32*)&sAl[(ra + 8) * KA + k0];
            al[2] = *(const u32*)&sAl[ra * KA + k0 + 8];
            al[3] = *(const u32*)&sAl[(ra + 8) * KA + k0 + 8];
            const uint4* fb = (const uint4*)&g_WoF[(((ns * 6 + ks) * 4) * 32 + lane) * 4];
            #pragma unroll
            for (int nt = 0; nt < 4; nt++) {
                const uint4 b = fb[nt * 32];
                mma_bf16(c[nt], ah, b.x, b.y);
                mma_bf16(c[nt], ah, b.z, b.w);
                mma_bf16(c[nt], al, b.x, b.y);
            }
        }

        float* gout = out + wbase * (S_ * E_);
        #pragma unroll
        for (int nt = 0; nt < 4; nt++) {
            const int colb = 32 * ns + 8 * nt + 2 * t;
            const float2 bb = *(const float2*)&bo[colb];
            const int row0 = 16 * mi + g;
            if (row0 < ROWS)
                *(float2*)&gout[row0 * E_ + colb] =
                    make_float2(c[nt][0] + bb.x, c[nt][1] + bb.y);
            const int row1 = row0 + 8;
            if (row1 < ROWS)
                *(float2*)&gout[row1 * E_ + colb] =
                    make_float2(c[nt][2] + bb.x, c[nt][3] + bb.y);
        }
    }
}

extern "C" void kernel_launch(void* const* d_in, const int* in_sizes, int n_in,
                              void* d_out, int out_size)
{
    const float* X    = (const float*)d_in[0];
    const float* Wqkv = (const float*)d_in[1];
    const float* bqkv = (const float*)d_in[2];
    const float* Wo   = (const float*)d_in[3];
    const float* bo   = (const float*)d_in[4];
    const float* posb = (const float*)d_in[5];
    float* out = (float*)d_out;

    // rewrite weights into fragment order (same stream -> ordered before main)
    prep_frag<<<(NFRAG_Q * 128 + 255) / 256, 256>>>(Wqkv, Wo);

    cudaFuncSetAttribute(swin_msa_kernel,
                         cudaFuncAttributeMaxDynamicSharedMemorySize, SMEM_BYTES);

    const int n_windows = in_sizes[0] / (S_ * E_);   // 65536
    const int grid = n_windows / WPB;                // 16384
    swin_msa_kernel<<<grid, NTHREADS, SMEM_BYTES>>>(X, bqkv, bo, posb, out);
}